// round 1
// baseline (speedup 1.0000x reference)
#include <cuda_runtime.h>

#define N_HEAD 16
#define C_EMBD 1024
#define HD     64
#define BATCH  4
#define SEQ    2048
#define MTOT   (BATCH * SEQ)   // 8192

// Scratch (device globals: allocation-free)
__device__ float g_Q[BATCH * N_HEAD * SEQ * HD];
__device__ float g_K[BATCH * N_HEAD * SEQ * HD];
__device__ float g_V[BATCH * N_HEAD * SEQ * HD];
__device__ float g_Y[MTOT * C_EMBD];

// ---------------------------------------------------------------------------
// SGEMM: C[M,N] = A[M,K] @ B[K,N] + bias[N]
// MODE 0: A = x, epilogue scatters into g_Q/g_K/g_V ([B,H,T,hd] layout)
// MODE 1: A = g_Y, epilogue writes Cout row-major
// ---------------------------------------------------------------------------
#define BM 128
#define BN 128
#define BK 8
#define TM 8
#define TN 8

template <int MODE>
__global__ __launch_bounds__(256)
void sgemm_kernel(const float* __restrict__ Ain, const float* __restrict__ Bw,
                  const float* __restrict__ bias, float* __restrict__ Cout,
                  int M, int N, int K)
{
    const float* A = (MODE == 1) ? (const float*)g_Y : Ain;

    __shared__ float As[BK][BM];
    __shared__ float Bs[BK][BN];

    int tid = threadIdx.x;
    int bm = blockIdx.y * BM;
    int bn = blockIdx.x * BN;

    int a_row = tid >> 1;            // 0..127
    int a_col = (tid & 1) * 4;       // 0 or 4
    int b_row = tid >> 5;            // 0..7
    int b_col = (tid & 31) * 4;      // 0..124

    int tr = (tid >> 4) * TM;        // 0..120
    int tc = (tid & 15) * TN;        // 0..120

    const float* Ap = A + (size_t)(bm + a_row) * K + a_col;
    const float* Bp = Bw + (size_t)b_row * N + bn + b_col;

    float acc[TM][TN];
#pragma unroll
    for (int i = 0; i < TM; i++)
#pragma unroll
        for (int j = 0; j < TN; j++) acc[i][j] = 0.0f;

    for (int k0 = 0; k0 < K; k0 += BK) {
        float4 av = *(const float4*)(Ap + k0);
        float4 bv = *(const float4*)(Bp + (size_t)k0 * N);
        As[a_col + 0][a_row] = av.x;
        As[a_col + 1][a_row] = av.y;
        As[a_col + 2][a_row] = av.z;
        As[a_col + 3][a_row] = av.w;
        *(float4*)&Bs[b_row][b_col] = bv;
        __syncthreads();

#pragma unroll
        for (int kk = 0; kk < BK; kk++) {
            float ar[TM], br[TN];
            *(float4*)&ar[0] = *(const float4*)&As[kk][tr];
            *(float4*)&ar[4] = *(const float4*)&As[kk][tr + 4];
            *(float4*)&br[0] = *(const float4*)&Bs[kk][tc];
            *(float4*)&br[4] = *(const float4*)&Bs[kk][tc + 4];
#pragma unroll
            for (int i = 0; i < TM; i++)
#pragma unroll
                for (int j = 0; j < TN; j++)
                    acc[i][j] = fmaf(ar[i], br[j], acc[i][j]);
        }
        __syncthreads();
    }

#pragma unroll
    for (int i = 0; i < TM; i++) {
        int m = bm + tr + i;
#pragma unroll
        for (int j = 0; j < TN; j++) {
            int n = bn + tc + j;
            float v = acc[i][j] + bias[n];
            if (MODE == 0) {
                int which = n >> 10;       // 0=Q 1=K 2=V
                int cc = n & 1023;
                int h = cc >> 6;
                int d = cc & 63;
                int bb = m >> 11;          // batch
                int t  = m & 2047;         // token
                float* dst = (which == 0) ? g_Q : (which == 1) ? g_K : g_V;
                dst[((((size_t)bb * N_HEAD) + h) * SEQ + t) * HD + d] = v;
            } else {
                Cout[(size_t)m * N + n] = v;
            }
        }
    }
}

// ---------------------------------------------------------------------------
// Flash attention (fp32, online softmax), one CTA per (b*h, 64-query block).
// Q and K held d-major (transposed) in smem: inner product loop is
// 2x LDS.128 + 16 FMA per d, conflict-free. Causal: only kb <= qb visited.
// ---------------------------------------------------------------------------
#define FP 68   // smem pitch (floats)

__global__ __launch_bounds__(256)
void flash_kernel()
{
    extern __shared__ float sm[];
    float* Qt = sm;                 // [64 d][FP]  (col = query row)
    float* Kt = sm + 64 * FP;       // [64 d][FP]  (col = key row)
    float* Vs = sm + 2 * 64 * FP;   // [64 k][FP]  (col = dim)
    float* Ps = sm + 3 * 64 * FP;   // [64 r][FP]  (col = key)

    int tid = threadIdx.x;
    int tx = tid & 15;
    int ty = tid >> 4;
    int r0 = ty * 4;                // query rows owned
    int c0 = tx * 4;                // key cols owned (S phase)
    int d0 = tx * 4;                // dims owned (O phase)

    int qb = blockIdx.x;
    int bh = blockIdx.y;
    int q0 = qb * 64;
    size_t base = (size_t)bh * SEQ * HD;
    const float* Qg = g_Q + base;
    const float* Kg = g_K + base;
    const float* Vg = g_V + base;

    // Load Q tile transposed: Qt[d][t]
    {
        int t  = tid & 63;
        int db = (tid >> 6) * 4;
#pragma unroll
        for (int it = 0; it < 4; it++) {
            int dd = db + it * 16;
            float4 v = *(const float4*)(Qg + (size_t)(q0 + t) * HD + dd);
            Qt[(dd + 0) * FP + t] = v.x;
            Qt[(dd + 1) * FP + t] = v.y;
            Qt[(dd + 2) * FP + t] = v.z;
            Qt[(dd + 3) * FP + t] = v.w;
        }
    }

    float mrow[4], lrow[4], Oacc[4][4];
#pragma unroll
    for (int i = 0; i < 4; i++) {
        mrow[i] = -1e30f;
        lrow[i] = 0.0f;
#pragma unroll
        for (int j = 0; j < 4; j++) Oacc[i][j] = 0.0f;
    }

    __syncthreads();

    for (int kb = 0; kb <= qb; kb++) {
        int k0 = kb * 64;
        // Load K transposed + V natural
        {
            int t  = tid & 63;
            int db = (tid >> 6) * 4;
#pragma unroll
            for (int it = 0; it < 4; it++) {
                int dd = db + it * 16;
                float4 v = *(const float4*)(Kg + (size_t)(k0 + t) * HD + dd);
                Kt[(dd + 0) * FP + t] = v.x;
                Kt[(dd + 1) * FP + t] = v.y;
                Kt[(dd + 2) * FP + t] = v.z;
                Kt[(dd + 3) * FP + t] = v.w;
            }
#pragma unroll
            for (int it = 0; it < 4; it++) {
                int f = tid + 256 * it;
                int kk = f >> 4;
                int dv = (f & 15) * 4;
                float4 v = *(const float4*)(Vg + (size_t)(k0 + kk) * HD + dv);
                *(float4*)&Vs[kk * FP + dv] = v;
            }
        }
        __syncthreads();

        // S = Q @ K^T (4x4 per thread)
        float acc[4][4];
#pragma unroll
        for (int i = 0; i < 4; i++)
#pragma unroll
            for (int j = 0; j < 4; j++) acc[i][j] = 0.0f;

#pragma unroll 8
        for (int d = 0; d < HD; d++) {
            float4 qv = *(const float4*)&Qt[d * FP + r0];
            float4 kv = *(const float4*)&Kt[d * FP + c0];
            float qa[4] = {qv.x, qv.y, qv.z, qv.w};
            float ka[4] = {kv.x, kv.y, kv.z, kv.w};
#pragma unroll
            for (int i = 0; i < 4; i++)
#pragma unroll
                for (int j = 0; j < 4; j++)
                    acc[i][j] = fmaf(qa[i], ka[j], acc[i][j]);
        }

        // scale + causal mask (only the diagonal block needs masking)
        bool diag = (kb == qb);
#pragma unroll
        for (int i = 0; i < 4; i++)
#pragma unroll
            for (int j = 0; j < 4; j++) {
                float s = acc[i][j] * 0.125f;   // 1/sqrt(64)
                if (diag && (c0 + j > r0 + i)) s = -1e30f;
                acc[i][j] = s;
            }

        // online softmax (row reductions across the 16 tx lanes)
#pragma unroll
        for (int i = 0; i < 4; i++) {
            float rmax = fmaxf(fmaxf(acc[i][0], acc[i][1]),
                               fmaxf(acc[i][2], acc[i][3]));
#pragma unroll
            for (int off = 8; off >= 1; off >>= 1)
                rmax = fmaxf(rmax, __shfl_xor_sync(0xffffffffu, rmax, off));
            float mnew = fmaxf(mrow[i], rmax);
            float rsum = 0.0f;
#pragma unroll
            for (int j = 0; j < 4; j++) {
                float p = __expf(acc[i][j] - mnew);
                acc[i][j] = p;
                rsum += p;
            }
#pragma unroll
            for (int off = 8; off >= 1; off >>= 1)
                rsum += __shfl_xor_sync(0xffffffffu, rsum, off);
            float corr = __expf(mrow[i] - mnew);
            lrow[i] = lrow[i] * corr + rsum;
            mrow[i] = mnew;
#pragma unroll
            for (int j = 0; j < 4; j++) Oacc[i][j] *= corr;
        }

        // write P
#pragma unroll
        for (int i = 0; i < 4; i++)
            *(float4*)&Ps[(r0 + i) * FP + c0] =
                make_float4(acc[i][0], acc[i][1], acc[i][2], acc[i][3]);
        __syncthreads();

        // O += P @ V
#pragma unroll 4
        for (int k = 0; k < 64; k++) {
            float4 vv = *(const float4*)&Vs[k * FP + d0];
            float p0 = Ps[(r0 + 0) * FP + k];
            float p1 = Ps[(r0 + 1) * FP + k];
            float p2 = Ps[(r0 + 2) * FP + k];
            float p3 = Ps[(r0 + 3) * FP + k];
            Oacc[0][0] = fmaf(p0, vv.x, Oacc[0][0]);
            Oacc[0][1] = fmaf(p0, vv.y, Oacc[0][1]);
            Oacc[0][2] = fmaf(p0, vv.z, Oacc[0][2]);
            Oacc[0][3] = fmaf(p0, vv.w, Oacc[0][3]);
            Oacc[1][0] = fmaf(p1, vv.x, Oacc[1][0]);
            Oacc[1][1] = fmaf(p1, vv.y, Oacc[1][1]);
            Oacc[1][2] = fmaf(p1, vv.z, Oacc[1][2]);
            Oacc[1][3] = fmaf(p1, vv.w, Oacc[1][3]);
            Oacc[2][0] = fmaf(p2, vv.x, Oacc[2][0]);
            Oacc[2][1] = fmaf(p2, vv.y, Oacc[2][1]);
            Oacc[2][2] = fmaf(p2, vv.z, Oacc[2][2]);
            Oacc[2][3] = fmaf(p2, vv.w, Oacc[2][3]);
            Oacc[3][0] = fmaf(p3, vv.x, Oacc[3][0]);
            Oacc[3][1] = fmaf(p3, vv.y, Oacc[3][1]);
            Oacc[3][2] = fmaf(p3, vv.z, Oacc[3][2]);
            Oacc[3][3] = fmaf(p3, vv.w, Oacc[3][3]);
        }
        __syncthreads();
    }

    // normalize + write y in [B,T,C] layout
    int b = bh >> 4;
    int h = bh & 15;
#pragma unroll
    for (int i = 0; i < 4; i++) {
        float inv = 1.0f / lrow[i];
        int t = q0 + r0 + i;
        float4 o = make_float4(Oacc[i][0] * inv, Oacc[i][1] * inv,
                               Oacc[i][2] * inv, Oacc[i][3] * inv);
        *(float4*)&g_Y[((size_t)(b * SEQ + t)) * C_EMBD + h * HD + d0] = o;
    }
}

// ---------------------------------------------------------------------------
extern "C" void kernel_launch(void* const* d_in, const int* in_sizes, int n_in,
                              void* d_out, int out_size)
{
    const float* x      = (const float*)d_in[0];
    const float* W_attn = (const float*)d_in[1];
    const float* b_attn = (const float*)d_in[2];
    const float* W_proj = (const float*)d_in[3];
    const float* b_proj = (const float*)d_in[4];
    float* out = (float*)d_out;

    (void)in_sizes; (void)n_in; (void)out_size;

    static const int FLASH_SMEM = 4 * 64 * FP * sizeof(float);  // 69632 B
    cudaFuncSetAttribute(flash_kernel,
                         cudaFuncAttributeMaxDynamicSharedMemorySize, FLASH_SMEM);

    // 1) QKV GEMM + bias, scattered into Q/K/V [B,H,T,hd]
    dim3 g1(3 * C_EMBD / BN, MTOT / BM);   // (24, 64)
    sgemm_kernel<0><<<g1, 256>>>(x, W_attn, b_attn, nullptr,
                                 MTOT, 3 * C_EMBD, C_EMBD);

    // 2) causal flash attention -> g_Y [B,T,C]
    flash_kernel<<<dim3(SEQ / 64, BATCH * N_HEAD), 256, FLASH_SMEM>>>();

    // 3) output projection + bias -> d_out
    dim3 g2(C_EMBD / BN, MTOT / BM);       // (8, 64)
    sgemm_kernel<1><<<g2, 256>>>(nullptr, W_proj, b_proj, out,
                                 MTOT, C_EMBD, C_EMBD);
}

// round 5
// speedup vs baseline: 1.7416x; 1.7416x over previous
#include <cuda_runtime.h>
#include <cuda_bf16.h>
#include <cstdint>

#define N_HEAD 16
#define C_EMBD 1024
#define HD     64
#define BATCH  4
#define SEQ    2048
#define MTOT   (BATCH * SEQ)   // 8192

// ---------------- scratch (device globals: allocation-free) ----------------
__device__ float g_Q[BATCH * N_HEAD * SEQ * HD];
__device__ float g_K[BATCH * N_HEAD * SEQ * HD];
__device__ float g_V[BATCH * N_HEAD * SEQ * HD];

__device__ __nv_bfloat16 g_Xhi[MTOT * C_EMBD];
__device__ __nv_bfloat16 g_Xlo[MTOT * C_EMBD];
__device__ __nv_bfloat16 g_Yhi[MTOT * C_EMBD];
__device__ __nv_bfloat16 g_Ylo[MTOT * C_EMBD];
__device__ __nv_bfloat16 g_Wahi[3 * C_EMBD * C_EMBD];  // [N=3072][K=1024]
__device__ __nv_bfloat16 g_Walo[3 * C_EMBD * C_EMBD];
__device__ __nv_bfloat16 g_Wphi[C_EMBD * C_EMBD];      // [N=1024][K=1024]
__device__ __nv_bfloat16 g_Wplo[C_EMBD * C_EMBD];

// ---------------- helpers ----------------
__device__ __forceinline__ uint32_t smem_u32(const void* p) {
    uint32_t a;
    asm("{ .reg .u64 t; cvta.to.shared.u64 t, %1; cvt.u32.u64 %0, t; }" : "=r"(a) : "l"(p));
    return a;
}

__device__ __forceinline__ void ldsm_x4(uint32_t& r0, uint32_t& r1,
                                        uint32_t& r2, uint32_t& r3, uint32_t addr) {
    asm volatile("ldmatrix.sync.aligned.m8n8.x4.shared.b16 {%0,%1,%2,%3}, [%4];"
                 : "=r"(r0), "=r"(r1), "=r"(r2), "=r"(r3) : "r"(addr));
}

__device__ __forceinline__ void mma_bf16(float* c, const uint32_t* a, const uint32_t* b) {
    asm volatile(
        "mma.sync.aligned.m16n8k16.row.col.f32.bf16.bf16.f32 "
        "{%0,%1,%2,%3}, {%4,%5,%6,%7}, {%8,%9}, {%0,%1,%2,%3};"
        : "+f"(c[0]), "+f"(c[1]), "+f"(c[2]), "+f"(c[3])
        : "r"(a[0]), "r"(a[1]), "r"(a[2]), "r"(a[3]), "r"(b[0]), "r"(b[1]));
}

// ---------------- prep kernels ----------------
__global__ __launch_bounds__(256)
void split_x_kernel(const float* __restrict__ X) {
    int i = blockIdx.x * 256 + threadIdx.x;           // float4 index
    float4 v = ((const float4*)X)[i];
    __nv_bfloat16 h0 = __float2bfloat16(v.x), h1 = __float2bfloat16(v.y);
    __nv_bfloat16 h2 = __float2bfloat16(v.z), h3 = __float2bfloat16(v.w);
    ((__nv_bfloat162*)g_Xhi)[2*i+0] = __nv_bfloat162(h0, h1);
    ((__nv_bfloat162*)g_Xhi)[2*i+1] = __nv_bfloat162(h2, h3);
    __nv_bfloat16 l0 = __float2bfloat16(v.x - __bfloat162float(h0));
    __nv_bfloat16 l1 = __float2bfloat16(v.y - __bfloat162float(h1));
    __nv_bfloat16 l2 = __float2bfloat16(v.z - __bfloat162float(h2));
    __nv_bfloat16 l3 = __float2bfloat16(v.w - __bfloat162float(h3));
    ((__nv_bfloat162*)g_Xlo)[2*i+0] = __nv_bfloat162(l0, l1);
    ((__nv_bfloat162*)g_Xlo)[2*i+1] = __nv_bfloat162(l2, l3);
}

// transpose + split:  W[K, N] fp32  ->  Wt_hi/lo[N, K] bf16
__global__ __launch_bounds__(256)
void wsplit_kernel(const float* __restrict__ W, int which, int N) {
    __shared__ float t[32][33];
    __nv_bfloat16* Hi = which ? g_Wphi : g_Wahi;
    __nv_bfloat16* Lo = which ? g_Wplo : g_Walo;
    const int K = C_EMBD;
    int n0 = blockIdx.x * 32, k0 = blockIdx.y * 32;
    int tx = threadIdx.x, ty = threadIdx.y;
#pragma unroll
    for (int s = 0; s < 4; s++) {
        int i = ty + 8 * s;
        t[i][tx] = W[(size_t)(k0 + i) * N + n0 + tx];
    }
    __syncthreads();
#pragma unroll
    for (int s = 0; s < 4; s++) {
        int i = ty + 8 * s;
        float v = t[tx][i];                            // W[k0+tx][n0+i]
        __nv_bfloat16 h = __float2bfloat16(v);
        Hi[(size_t)(n0 + i) * K + k0 + tx] = h;
        Lo[(size_t)(n0 + i) * K + k0 + tx] = __float2bfloat16(v - __bfloat162float(h));
    }
}

// ---------------- HMMA GEMM (bf16x3, fp32 accumulate) ----------------
// C[M,N] = A[M,K] @ B[N,K]^T + bias ;  A = hi+lo, B = hi+lo, 3 passes.
// CTA tile 128x128, BK=32, double-buffered smem, warps 4(M) x 2(N).
#define BKC     32
#define NCHUNK  (C_EMBD / BKC)          // 32
#define ROWB    80                       // smem row pitch bytes (32 bf16 + pad)
#define MATB    (128 * ROWB)             // 10240 B per matrix tile
#define STAGEB  (4 * MATB)               // Ah, Al, Bh, Bl
#define AH_OFF  0
#define AL_OFF  MATB
#define BH_OFF  (2 * MATB)
#define BL_OFF  (3 * MATB)

template <int MODE>   // 0: QKV gemm (scatter to Q/K/V), 1: proj gemm (write Cout)
__global__ __launch_bounds__(256, 1)
void mma_gemm(const float* __restrict__ bias, float* __restrict__ Cout, int N)
{
    extern __shared__ char smem[];

    const __nv_bfloat16* Ahi = (MODE == 0) ? g_Xhi : g_Yhi;
    const __nv_bfloat16* Alo = (MODE == 0) ? g_Xlo : g_Ylo;
    const __nv_bfloat16* Bhi = (MODE == 0) ? g_Wahi : g_Wphi;
    const __nv_bfloat16* Blo = (MODE == 0) ? g_Walo : g_Wplo;

    const int K = C_EMBD;
    int tid = threadIdx.x;
    int lane = tid & 31, wid = tid >> 5;
    int wm = wid & 3, wn = wid >> 2;                   // warp tile: 32(M) x 64(N)
    int bn = blockIdx.x * 128;
    int bm = blockIdx.y * 128;

    uint32_t sb = smem_u32(smem);

    // gmem load mapping: id in [0,512): r=id>>2 (row), q=id&3 (16B slot)
    int r_ld = tid >> 2;
    int q_ld = tid & 3;
    const __nv_bfloat16* pAh = Ahi + (size_t)(bm + r_ld) * K + q_ld * 8;
    const __nv_bfloat16* pAl = Alo + (size_t)(bm + r_ld) * K + q_ld * 8;
    const __nv_bfloat16* pBh = Bhi + (size_t)(bn + r_ld) * K + q_ld * 8;
    const __nv_bfloat16* pBl = Blo + (size_t)(bn + r_ld) * K + q_ld * 8;
    const __nv_bfloat16* pAh2 = Ahi + (size_t)(bm + r_ld + 64) * K + q_ld * 8;
    const __nv_bfloat16* pAl2 = Alo + (size_t)(bm + r_ld + 64) * K + q_ld * 8;
    const __nv_bfloat16* pBh2 = Bhi + (size_t)(bn + r_ld + 64) * K + q_ld * 8;
    const __nv_bfloat16* pBl2 = Blo + (size_t)(bn + r_ld + 64) * K + q_ld * 8;
    uint32_t st1 = (uint32_t)(r_ld * ROWB + q_ld * 16);
    uint32_t st2 = (uint32_t)((r_ld + 64) * ROWB + q_ld * 16);

    // ldmatrix addresses (within-tile, bytes)
    uint32_t a_row = (uint32_t)(wm * 32 + (lane & 15));          // + mf*16
    uint32_t a_colb = (uint32_t)(((lane >> 4) << 3) * 2);        // + kstep*2
    int bq = lane >> 3;
    uint32_t b_row = (uint32_t)(wn * 64 + ((bq >> 1) << 3) + (lane & 7));  // + nb*16
    uint32_t b_colb = (uint32_t)(((bq & 1) << 3) * 2);                     // + kstep*2

    float acc[2][8][4];
#pragma unroll
    for (int i = 0; i < 2; i++)
#pragma unroll
        for (int j = 0; j < 8; j++)
#pragma unroll
            for (int k = 0; k < 4; k++) acc[i][j][k] = 0.0f;

    // prologue: chunk 0 -> stage 0
    {
        char* s = smem;
        *(uint4*)(s + AH_OFF + st1) = *(const uint4*)pAh;
        *(uint4*)(s + AH_OFF + st2) = *(const uint4*)pAh2;
        *(uint4*)(s + AL_OFF + st1) = *(const uint4*)pAl;
        *(uint4*)(s + AL_OFF + st2) = *(const uint4*)pAl2;
        *(uint4*)(s + BH_OFF + st1) = *(const uint4*)pBh;
        *(uint4*)(s + BH_OFF + st2) = *(const uint4*)pBh2;
        *(uint4*)(s + BL_OFF + st1) = *(const uint4*)pBl;
        *(uint4*)(s + BL_OFF + st2) = *(const uint4*)pBl2;
    }
    __syncthreads();

    for (int ch = 0; ch < NCHUNK; ch++) {
        uint32_t stage = (uint32_t)(ch & 1) * STAGEB;

        // prefetch next chunk to regs
        uint4 nAh1, nAh2, nAl1, nAl2, nBh1, nBh2, nBl1, nBl2;
        bool havenext = (ch + 1 < NCHUNK);
        if (havenext) {
            int k0 = (ch + 1) * BKC;
            nAh1 = *(const uint4*)(pAh + k0);  nAh2 = *(const uint4*)(pAh2 + k0);
            nAl1 = *(const uint4*)(pAl + k0);  nAl2 = *(const uint4*)(pAl2 + k0);
            nBh1 = *(const uint4*)(pBh + k0);  nBh2 = *(const uint4*)(pBh2 + k0);
            nBl1 = *(const uint4*)(pBl + k0);  nBl2 = *(const uint4*)(pBl2 + k0);
        }

        // compute current chunk (2 k-steps of 16)
#pragma unroll
        for (int ks = 0; ks < 2; ks++) {
            uint32_t kb = (uint32_t)(ks * 16 * 2);   // byte offset of k-step
            uint32_t ah[2][4], al[2][4];
#pragma unroll
            for (int mf = 0; mf < 2; mf++) {
                uint32_t ra = sb + stage + (a_row + mf * 16) * ROWB + a_colb + kb;
                ldsm_x4(ah[mf][0], ah[mf][1], ah[mf][2], ah[mf][3], ra + AH_OFF);
                ldsm_x4(al[mf][0], al[mf][1], al[mf][2], al[mf][3], ra + AL_OFF);
            }
            uint32_t bh[8][2], bl[8][2];
#pragma unroll
            for (int nb = 0; nb < 4; nb++) {
                uint32_t rb = sb + stage + (b_row + nb * 16) * ROWB + b_colb + kb;
                ldsm_x4(bh[2*nb][0], bh[2*nb][1], bh[2*nb+1][0], bh[2*nb+1][1], rb + BH_OFF);
                ldsm_x4(bl[2*nb][0], bl[2*nb][1], bl[2*nb+1][0], bl[2*nb+1][1], rb + BL_OFF);
            }
#pragma unroll
            for (int mf = 0; mf < 2; mf++)
#pragma unroll
                for (int nf = 0; nf < 8; nf++) {
                    mma_bf16(acc[mf][nf], ah[mf], bh[nf]);
                    mma_bf16(acc[mf][nf], ah[mf], bl[nf]);
                    mma_bf16(acc[mf][nf], al[mf], bh[nf]);
                }
        }

        if (havenext) {
            __syncthreads();
            char* s = smem + (((ch + 1) & 1) ? STAGEB : 0);
            *(uint4*)(s + AH_OFF + st1) = nAh1;  *(uint4*)(s + AH_OFF + st2) = nAh2;
            *(uint4*)(s + AL_OFF + st1) = nAl1;  *(uint4*)(s + AL_OFF + st2) = nAl2;
            *(uint4*)(s + BH_OFF + st1) = nBh1;  *(uint4*)(s + BH_OFF + st2) = nBh2;
            *(uint4*)(s + BL_OFF + st1) = nBl1;  *(uint4*)(s + BL_OFF + st2) = nBl2;
            __syncthreads();
        }
    }

    // epilogue: bias + write
#pragma unroll
    for (int mf = 0; mf < 2; mf++) {
#pragma unroll
        for (int nf = 0; nf < 8; nf++) {
            int m0 = bm + wm * 32 + mf * 16 + (lane >> 2);
            int n0 = bn + wn * 64 + nf * 8 + 2 * (lane & 3);
#pragma unroll
            for (int half = 0; half < 2; half++) {
                int m = m0 + half * 8;
                float v0 = acc[mf][nf][2 * half + 0] + bias[n0];
                float v1 = acc[mf][nf][2 * half + 1] + bias[n0 + 1];
                if (MODE == 0) {
                    int bb = m >> 11, t = m & 2047;
#pragma unroll
                    for (int e = 0; e < 2; e++) {
                        int n = n0 + e;
                        float v = e ? v1 : v0;
                        int which = n >> 10;
                        int cc = n & 1023;
                        int h = cc >> 6, d = cc & 63;
                        float* dst = (which == 0) ? g_Q : (which == 1) ? g_K : g_V;
                        dst[((((size_t)bb * N_HEAD) + h) * SEQ + t) * HD + d] = v;
                    }
                } else {
                    *(float2*)&Cout[(size_t)m * N + n0] = make_float2(v0, v1);
                }
            }
        }
    }
}

// ---------------------------------------------------------------------------
// Flash attention (fp32, online softmax), one CTA per (b*h, 64-query block).
// ---------------------------------------------------------------------------
#define FP 68   // smem pitch (floats)

__global__ __launch_bounds__(256)
void flash_kernel()
{
    extern __shared__ float sm[];
    float* Qt = sm;
    float* Kt = sm + 64 * FP;
    float* Vs = sm + 2 * 64 * FP;
    float* Ps = sm + 3 * 64 * FP;

    int tid = threadIdx.x;
    int tx = tid & 15;
    int ty = tid >> 4;
    int r0 = ty * 4;
    int c0 = tx * 4;
    int d0 = tx * 4;

    int qb = blockIdx.x;
    int bh = blockIdx.y;
    int q0 = qb * 64;
    size_t base = (size_t)bh * SEQ * HD;
    const float* Qg = g_Q + base;
    const float* Kg = g_K + base;
    const float* Vg = g_V + base;

    {
        int t  = tid & 63;
        int db = (tid >> 6) * 4;
#pragma unroll
        for (int it = 0; it < 4; it++) {
            int dd = db + it * 16;
            float4 v = *(const float4*)(Qg + (size_t)(q0 + t) * HD + dd);
            Qt[(dd + 0) * FP + t] = v.x;
            Qt[(dd + 1) * FP + t] = v.y;
            Qt[(dd + 2) * FP + t] = v.z;
            Qt[(dd + 3) * FP + t] = v.w;
        }
    }

    float mrow[4], lrow[4], Oacc[4][4];
#pragma unroll
    for (int i = 0; i < 4; i++) {
        mrow[i] = -1e30f;
        lrow[i] = 0.0f;
#pragma unroll
        for (int j = 0; j < 4; j++) Oacc[i][j] = 0.0f;
    }

    __syncthreads();

    for (int kb = 0; kb <= qb; kb++) {
        int k0 = kb * 64;
        {
            int t  = tid & 63;
            int db = (tid >> 6) * 4;
#pragma unroll
            for (int it = 0; it < 4; it++) {
                int dd = db + it * 16;
                float4 v = *(const float4*)(Kg + (size_t)(k0 + t) * HD + dd);
                Kt[(dd + 0) * FP + t] = v.x;
                Kt[(dd + 1) * FP + t] = v.y;
                Kt[(dd + 2) * FP + t] = v.z;
                Kt[(dd + 3) * FP + t] = v.w;
            }
#pragma unroll
            for (int it = 0; it < 4; it++) {
                int f = tid + 256 * it;
                int kk = f >> 4;
                int dv = (f & 15) * 4;
                float4 v = *(const float4*)(Vg + (size_t)(k0 + kk) * HD + dv);
                *(float4*)&Vs[kk * FP + dv] = v;
            }
        }
        __syncthreads();

        float acc[4][4];
#pragma unroll
        for (int i = 0; i < 4; i++)
#pragma unroll
            for (int j = 0; j < 4; j++) acc[i][j] = 0.0f;

#pragma unroll 8
        for (int d = 0; d < HD; d++) {
            float4 qv = *(const float4*)&Qt[d * FP + r0];
            float4 kv = *(const float4*)&Kt[d * FP + c0];
            float qa[4] = {qv.x, qv.y, qv.z, qv.w};
            float ka[4] = {kv.x, kv.y, kv.z, kv.w};
#pragma unroll
            for (int i = 0; i < 4; i++)
#pragma unroll
                for (int j = 0; j < 4; j++)
                    acc[i][j] = fmaf(qa[i], ka[j], acc[i][j]);
        }

        bool diag = (kb == qb);
#pragma unroll
        for (int i = 0; i < 4; i++)
#pragma unroll
            for (int j = 0; j < 4; j++) {
                float s = acc[i][j] * 0.125f;
                if (diag && (c0 + j > r0 + i)) s = -1e30f;
                acc[i][j] = s;
            }

#pragma unroll
        for (int i = 0; i < 4; i++) {
            float rmax = fmaxf(fmaxf(acc[i][0], acc[i][1]),
                               fmaxf(acc[i][2], acc[i][3]));
#pragma unroll
            for (int off = 8; off >= 1; off >>= 1)
                rmax = fmaxf(rmax, __shfl_xor_sync(0xffffffffu, rmax, off));
            float mnew = fmaxf(mrow[i], rmax);
            float rsum = 0.0f;
#pragma unroll
            for (int j = 0; j < 4; j++) {
                float p = __expf(acc[i][j] - mnew);
                acc[i][j] = p;
                rsum += p;
            }
#pragma unroll
            for (int off = 8; off >= 1; off >>= 1)
                rsum += __shfl_xor_sync(0xffffffffu, rsum, off);
            float corr = __expf(mrow[i] - mnew);
            lrow[i] = lrow[i] * corr + rsum;
            mrow[i] = mnew;
#pragma unroll
            for (int j = 0; j < 4; j++) Oacc[i][j] *= corr;
        }

#pragma unroll
        for (int i = 0; i < 4; i++)
            *(float4*)&Ps[(r0 + i) * FP + c0] =
                make_float4(acc[i][0], acc[i][1], acc[i][2], acc[i][3]);
        __syncthreads();

#pragma unroll 4
        for (int k = 0; k < 64; k++) {
            float4 vv = *(const float4*)&Vs[k * FP + d0];
            float p0 = Ps[(r0 + 0) * FP + k];
            float p1 = Ps[(r0 + 1) * FP + k];
            float p2 = Ps[(r0 + 2) * FP + k];
            float p3 = Ps[(r0 + 3) * FP + k];
            Oacc[0][0] = fmaf(p0, vv.x, Oacc[0][0]);
            Oacc[0][1] = fmaf(p0, vv.y, Oacc[0][1]);
            Oacc[0][2] = fmaf(p0, vv.z, Oacc[0][2]);
            Oacc[0][3] = fmaf(p0, vv.w, Oacc[0][3]);
            Oacc[1][0] = fmaf(p1, vv.x, Oacc[1][0]);
            Oacc[1][1] = fmaf(p1, vv.y, Oacc[1][1]);
            Oacc[1][2] = fmaf(p1, vv.z, Oacc[1][2]);
            Oacc[1][3] = fmaf(p1, vv.w, Oacc[1][3]);
            Oacc[2][0] = fmaf(p2, vv.x, Oacc[2][0]);
            Oacc[2][1] = fmaf(p2, vv.y, Oacc[2][1]);
            Oacc[2][2] = fmaf(p2, vv.z, Oacc[2][2]);
            Oacc[2][3] = fmaf(p2, vv.w, Oacc[2][3]);
            Oacc[3][0] = fmaf(p3, vv.x, Oacc[3][0]);
            Oacc[3][1] = fmaf(p3, vv.y, Oacc[3][1]);
            Oacc[3][2] = fmaf(p3, vv.z, Oacc[3][2]);
            Oacc[3][3] = fmaf(p3, vv.w, Oacc[3][3]);
        }
        __syncthreads();
    }

    // normalize + write Y split to bf16 hi/lo for the projection GEMM
    int b = bh >> 4;
    int h = bh & 15;
#pragma unroll
    for (int i = 0; i < 4; i++) {
        float inv = 1.0f / lrow[i];
        int t = q0 + r0 + i;
        size_t idx = ((size_t)(b * SEQ + t)) * C_EMBD + h * HD + d0;
        float o0 = Oacc[i][0] * inv, o1 = Oacc[i][1] * inv;
        float o2 = Oacc[i][2] * inv, o3 = Oacc[i][3] * inv;
        __nv_bfloat16 h0 = __float2bfloat16(o0), h1 = __float2bfloat16(o1);
        __nv_bfloat16 h2 = __float2bfloat16(o2), h3 = __float2bfloat16(o3);
        *(__nv_bfloat162*)&g_Yhi[idx]     = __nv_bfloat162(h0, h1);
        *(__nv_bfloat162*)&g_Yhi[idx + 2] = __nv_bfloat162(h2, h3);
        __nv_bfloat16 l0 = __float2bfloat16(o0 - __bfloat162float(h0));
        __nv_bfloat16 l1 = __float2bfloat16(o1 - __bfloat162float(h1));
        __nv_bfloat16 l2 = __float2bfloat16(o2 - __bfloat162float(h2));
        __nv_bfloat16 l3 = __float2bfloat16(o3 - __bfloat162float(h3));
        *(__nv_bfloat162*)&g_Ylo[idx]     = __nv_bfloat162(l0, l1);
        *(__nv_bfloat162*)&g_Ylo[idx + 2] = __nv_bfloat162(l2, l3);
    }
}

// ---------------------------------------------------------------------------
extern "C" void kernel_launch(void* const* d_in, const int* in_sizes, int n_in,
                              void* d_out, int out_size)
{
    const float* x      = (const float*)d_in[0];
    const float* W_attn = (const float*)d_in[1];
    const float* b_attn = (const float*)d_in[2];
    const float* W_proj = (const float*)d_in[3];
    const float* b_proj = (const float*)d_in[4];
    float* out = (float*)d_out;

    (void)in_sizes; (void)n_in; (void)out_size;

    static const int FLASH_SMEM = 4 * 64 * FP * sizeof(float);      // 69632 B
    static const int GEMM_SMEM  = 2 * STAGEB;                       // 81920 B
    cudaFuncSetAttribute(flash_kernel,
                         cudaFuncAttributeMaxDynamicSharedMemorySize, FLASH_SMEM);
    cudaFuncSetAttribute(mma_gemm<0>,
                         cudaFuncAttributeMaxDynamicSharedMemorySize, GEMM_SMEM);
    cudaFuncSetAttribute(mma_gemm<1>,
                         cudaFuncAttributeMaxDynamicSharedMemorySize, GEMM_SMEM);

    // 0) prep: split x; transpose+split weights
    split_x_kernel<<<MTOT * C_EMBD / 4 / 256, 256>>>(x);
    wsplit_kernel<<<dim3(3 * C_EMBD / 32, C_EMBD / 32), dim3(32, 8)>>>(W_attn, 0, 3 * C_EMBD);
    wsplit_kernel<<<dim3(C_EMBD / 32, C_EMBD / 32), dim3(32, 8)>>>(W_proj, 1, C_EMBD);

    // 1) QKV GEMM (HMMA bf16x3) + bias -> scatter into Q/K/V [B,H,T,hd]
    mma_gemm<0><<<dim3(3 * C_EMBD / 128, MTOT / 128), 256, GEMM_SMEM>>>(
        b_attn, nullptr, 3 * C_EMBD);

    // 2) causal flash attention -> Yhi/Ylo (bf16 split)
    flash_kernel<<<dim3(SEQ / 64, BATCH * N_HEAD), 256, FLASH_SMEM>>>();

    // 3) output projection (HMMA bf16x3) + bias -> d_out
    mma_gemm<1><<<dim3(C_EMBD / 128, MTOT / 128), 256, GEMM_SMEM>>>(
        b_proj, out, C_EMBD);
}

// round 6
// speedup vs baseline: 3.1743x; 1.8226x over previous
#include <cuda_runtime.h>
#include <cuda_bf16.h>
#include <cstdint>

#define N_HEAD 16
#define C_EMBD 1024
#define HD     64
#define BATCH  4
#define SEQ    2048
#define MTOT   (BATCH * SEQ)   // 8192

// ---------------- scratch (device globals: allocation-free) ----------------
__device__ __nv_bfloat16 g_Qhi[BATCH * N_HEAD * SEQ * HD];
__device__ __nv_bfloat16 g_Qlo[BATCH * N_HEAD * SEQ * HD];
__device__ __nv_bfloat16 g_Khi[BATCH * N_HEAD * SEQ * HD];
__device__ __nv_bfloat16 g_Klo[BATCH * N_HEAD * SEQ * HD];
__device__ __nv_bfloat16 g_Vhi[BATCH * N_HEAD * SEQ * HD];
__device__ __nv_bfloat16 g_Vlo[BATCH * N_HEAD * SEQ * HD];

__device__ __nv_bfloat16 g_Xhi[MTOT * C_EMBD];
__device__ __nv_bfloat16 g_Xlo[MTOT * C_EMBD];
__device__ __nv_bfloat16 g_Yhi[MTOT * C_EMBD];
__device__ __nv_bfloat16 g_Ylo[MTOT * C_EMBD];
__device__ __nv_bfloat16 g_Wahi[3 * C_EMBD * C_EMBD];  // [N=3072][K=1024]
__device__ __nv_bfloat16 g_Walo[3 * C_EMBD * C_EMBD];
__device__ __nv_bfloat16 g_Wphi[C_EMBD * C_EMBD];      // [N=1024][K=1024]
__device__ __nv_bfloat16 g_Wplo[C_EMBD * C_EMBD];

// ---------------- helpers ----------------
__device__ __forceinline__ uint32_t smem_u32(const void* p) {
    uint32_t a;
    asm("{ .reg .u64 t; cvta.to.shared.u64 t, %1; cvt.u32.u64 %0, t; }" : "=r"(a) : "l"(p));
    return a;
}

__device__ __forceinline__ void ldsm_x4(uint32_t& r0, uint32_t& r1,
                                        uint32_t& r2, uint32_t& r3, uint32_t addr) {
    asm volatile("ldmatrix.sync.aligned.m8n8.x4.shared.b16 {%0,%1,%2,%3}, [%4];"
                 : "=r"(r0), "=r"(r1), "=r"(r2), "=r"(r3) : "r"(addr));
}

__device__ __forceinline__ void ldsm_x4_t(uint32_t& r0, uint32_t& r1,
                                          uint32_t& r2, uint32_t& r3, uint32_t addr) {
    asm volatile("ldmatrix.sync.aligned.m8n8.x4.trans.shared.b16 {%0,%1,%2,%3}, [%4];"
                 : "=r"(r0), "=r"(r1), "=r"(r2), "=r"(r3) : "r"(addr));
}

__device__ __forceinline__ void mma_bf16(float* c, const uint32_t* a, const uint32_t* b) {
    asm volatile(
        "mma.sync.aligned.m16n8k16.row.col.f32.bf16.bf16.f32 "
        "{%0,%1,%2,%3}, {%4,%5,%6,%7}, {%8,%9}, {%0,%1,%2,%3};"
        : "+f"(c[0]), "+f"(c[1]), "+f"(c[2]), "+f"(c[3])
        : "r"(a[0]), "r"(a[1]), "r"(a[2]), "r"(a[3]), "r"(b[0]), "r"(b[1]));
}

// split two floats into bf16 hi pair + bf16 lo (residual) pair, packed b16x2
__device__ __forceinline__ void split2(float x, float y, uint32_t& hi, uint32_t& lo) {
    __nv_bfloat162 h = __floats2bfloat162_rn(x, y);
    __nv_bfloat162 l = __floats2bfloat162_rn(x - __bfloat162float(h.x),
                                             y - __bfloat162float(h.y));
    hi = *(uint32_t*)&h;
    lo = *(uint32_t*)&l;
}

// ---------------- prep kernels ----------------
__global__ __launch_bounds__(256)
void split_x_kernel(const float* __restrict__ X) {
    int i = blockIdx.x * 256 + threadIdx.x;           // float4 index
    float4 v = ((const float4*)X)[i];
    __nv_bfloat16 h0 = __float2bfloat16(v.x), h1 = __float2bfloat16(v.y);
    __nv_bfloat16 h2 = __float2bfloat16(v.z), h3 = __float2bfloat16(v.w);
    ((__nv_bfloat162*)g_Xhi)[2*i+0] = __nv_bfloat162(h0, h1);
    ((__nv_bfloat162*)g_Xhi)[2*i+1] = __nv_bfloat162(h2, h3);
    __nv_bfloat16 l0 = __float2bfloat16(v.x - __bfloat162float(h0));
    __nv_bfloat16 l1 = __float2bfloat16(v.y - __bfloat162float(h1));
    __nv_bfloat16 l2 = __float2bfloat16(v.z - __bfloat162float(h2));
    __nv_bfloat16 l3 = __float2bfloat16(v.w - __bfloat162float(h3));
    ((__nv_bfloat162*)g_Xlo)[2*i+0] = __nv_bfloat162(l0, l1);
    ((__nv_bfloat162*)g_Xlo)[2*i+1] = __nv_bfloat162(l2, l3);
}

// transpose + split:  W[K, N] fp32  ->  Wt_hi/lo[N, K] bf16
__global__ __launch_bounds__(256)
void wsplit_kernel(const float* __restrict__ W, int which, int N) {
    __shared__ float t[32][33];
    __nv_bfloat16* Hi = which ? g_Wphi : g_Wahi;
    __nv_bfloat16* Lo = which ? g_Wplo : g_Walo;
    const int K = C_EMBD;
    int n0 = blockIdx.x * 32, k0 = blockIdx.y * 32;
    int tx = threadIdx.x, ty = threadIdx.y;
#pragma unroll
    for (int s = 0; s < 4; s++) {
        int i = ty + 8 * s;
        t[i][tx] = W[(size_t)(k0 + i) * N + n0 + tx];
    }
    __syncthreads();
#pragma unroll
    for (int s = 0; s < 4; s++) {
        int i = ty + 8 * s;
        float v = t[tx][i];                            // W[k0+tx][n0+i]
        __nv_bfloat16 h = __float2bfloat16(v);
        Hi[(size_t)(n0 + i) * K + k0 + tx] = h;
        Lo[(size_t)(n0 + i) * K + k0 + tx] = __float2bfloat16(v - __bfloat162float(h));
    }
}

// ---------------- HMMA GEMM (bf16x3, fp32 accumulate) ----------------
#define BKC     32
#define NCHUNK  (C_EMBD / BKC)          // 32
#define ROWB    80
#define MATB    (128 * ROWB)
#define STAGEB  (4 * MATB)
#define AH_OFF  0
#define AL_OFF  MATB
#define BH_OFF  (2 * MATB)
#define BL_OFF  (3 * MATB)

template <int MODE>   // 0: QKV gemm (split-scatter to Q/K/V hi/lo), 1: proj gemm
__global__ __launch_bounds__(256, 1)
void mma_gemm(const float* __restrict__ bias, float* __restrict__ Cout, int N)
{
    extern __shared__ char smem[];

    const __nv_bfloat16* Ahi = (MODE == 0) ? g_Xhi : g_Yhi;
    const __nv_bfloat16* Alo = (MODE == 0) ? g_Xlo : g_Ylo;
    const __nv_bfloat16* Bhi = (MODE == 0) ? g_Wahi : g_Wphi;
    const __nv_bfloat16* Blo = (MODE == 0) ? g_Walo : g_Wplo;

    const int K = C_EMBD;
    int tid = threadIdx.x;
    int lane = tid & 31, wid = tid >> 5;
    int wm = wid & 3, wn = wid >> 2;
    int bn = blockIdx.x * 128;
    int bm = blockIdx.y * 128;

    uint32_t sb = smem_u32(smem);

    int r_ld = tid >> 2;
    int q_ld = tid & 3;
    const __nv_bfloat16* pAh = Ahi + (size_t)(bm + r_ld) * K + q_ld * 8;
    const __nv_bfloat16* pAl = Alo + (size_t)(bm + r_ld) * K + q_ld * 8;
    const __nv_bfloat16* pBh = Bhi + (size_t)(bn + r_ld) * K + q_ld * 8;
    const __nv_bfloat16* pBl = Blo + (size_t)(bn + r_ld) * K + q_ld * 8;
    const __nv_bfloat16* pAh2 = Ahi + (size_t)(bm + r_ld + 64) * K + q_ld * 8;
    const __nv_bfloat16* pAl2 = Alo + (size_t)(bm + r_ld + 64) * K + q_ld * 8;
    const __nv_bfloat16* pBh2 = Bhi + (size_t)(bn + r_ld + 64) * K + q_ld * 8;
    const __nv_bfloat16* pBl2 = Blo + (size_t)(bn + r_ld + 64) * K + q_ld * 8;
    uint32_t st1 = (uint32_t)(r_ld * ROWB + q_ld * 16);
    uint32_t st2 = (uint32_t)((r_ld + 64) * ROWB + q_ld * 16);

    uint32_t a_row = (uint32_t)(wm * 32 + (lane & 15));
    uint32_t a_colb = (uint32_t)(((lane >> 4) << 3) * 2);
    int bq = lane >> 3;
    uint32_t b_row = (uint32_t)(wn * 64 + ((bq >> 1) << 3) + (lane & 7));
    uint32_t b_colb = (uint32_t)(((bq & 1) << 3) * 2);

    float acc[2][8][4];
#pragma unroll
    for (int i = 0; i < 2; i++)
#pragma unroll
        for (int j = 0; j < 8; j++)
#pragma unroll
            for (int k = 0; k < 4; k++) acc[i][j][k] = 0.0f;

    {
        char* s = smem;
        *(uint4*)(s + AH_OFF + st1) = *(const uint4*)pAh;
        *(uint4*)(s + AH_OFF + st2) = *(const uint4*)pAh2;
        *(uint4*)(s + AL_OFF + st1) = *(const uint4*)pAl;
        *(uint4*)(s + AL_OFF + st2) = *(const uint4*)pAl2;
        *(uint4*)(s + BH_OFF + st1) = *(const uint4*)pBh;
        *(uint4*)(s + BH_OFF + st2) = *(const uint4*)pBh2;
        *(uint4*)(s + BL_OFF + st1) = *(const uint4*)pBl;
        *(uint4*)(s + BL_OFF + st2) = *(const uint4*)pBl2;
    }
    __syncthreads();

    for (int ch = 0; ch < NCHUNK; ch++) {
        uint32_t stage = (uint32_t)(ch & 1) * STAGEB;

        uint4 nAh1, nAh2, nAl1, nAl2, nBh1, nBh2, nBl1, nBl2;
        bool havenext = (ch + 1 < NCHUNK);
        if (havenext) {
            int k0 = (ch + 1) * BKC;
            nAh1 = *(const uint4*)(pAh + k0);  nAh2 = *(const uint4*)(pAh2 + k0);
            nAl1 = *(const uint4*)(pAl + k0);  nAl2 = *(const uint4*)(pAl2 + k0);
            nBh1 = *(const uint4*)(pBh + k0);  nBh2 = *(const uint4*)(pBh2 + k0);
            nBl1 = *(const uint4*)(pBl + k0);  nBl2 = *(const uint4*)(pBl2 + k0);
        }

#pragma unroll
        for (int ks = 0; ks < 2; ks++) {
            uint32_t kb = (uint32_t)(ks * 16 * 2);
            uint32_t ah[2][4], al[2][4];
#pragma unroll
            for (int mf = 0; mf < 2; mf++) {
                uint32_t ra = sb + stage + (a_row + mf * 16) * ROWB + a_colb + kb;
                ldsm_x4(ah[mf][0], ah[mf][1], ah[mf][2], ah[mf][3], ra + AH_OFF);
                ldsm_x4(al[mf][0], al[mf][1], al[mf][2], al[mf][3], ra + AL_OFF);
            }
            uint32_t bh[8][2], bl[8][2];
#pragma unroll
            for (int nb = 0; nb < 4; nb++) {
                uint32_t rb = sb + stage + (b_row + nb * 16) * ROWB + b_colb + kb;
                ldsm_x4(bh[2*nb][0], bh[2*nb][1], bh[2*nb+1][0], bh[2*nb+1][1], rb + BH_OFF);
                ldsm_x4(bl[2*nb][0], bl[2*nb][1], bl[2*nb+1][0], bl[2*nb+1][1], rb + BL_OFF);
            }
#pragma unroll
            for (int mf = 0; mf < 2; mf++)
#pragma unroll
                for (int nf = 0; nf < 8; nf++) {
                    mma_bf16(acc[mf][nf], ah[mf], bh[nf]);
                    mma_bf16(acc[mf][nf], ah[mf], bl[nf]);
                    mma_bf16(acc[mf][nf], al[mf], bh[nf]);
                }
        }

        if (havenext) {
            __syncthreads();
            char* s = smem + (((ch + 1) & 1) ? STAGEB : 0);
            *(uint4*)(s + AH_OFF + st1) = nAh1;  *(uint4*)(s + AH_OFF + st2) = nAh2;
            *(uint4*)(s + AL_OFF + st1) = nAl1;  *(uint4*)(s + AL_OFF + st2) = nAl2;
            *(uint4*)(s + BH_OFF + st1) = nBh1;  *(uint4*)(s + BH_OFF + st2) = nBh2;
            *(uint4*)(s + BL_OFF + st1) = nBl1;  *(uint4*)(s + BL_OFF + st2) = nBl2;
            __syncthreads();
        }
    }

    // epilogue: bias + write
#pragma unroll
    for (int mf = 0; mf < 2; mf++) {
#pragma unroll
        for (int nf = 0; nf < 8; nf++) {
            int m0 = bm + wm * 32 + mf * 16 + (lane >> 2);
            int n0 = bn + wn * 64 + nf * 8 + 2 * (lane & 3);
#pragma unroll
            for (int half = 0; half < 2; half++) {
                int m = m0 + half * 8;
                float v0 = acc[mf][nf][2 * half + 0] + bias[n0];
                float v1 = acc[mf][nf][2 * half + 1] + bias[n0 + 1];
                if (MODE == 0) {
                    int bb = m >> 11, t = m & 2047;
                    int which = n0 >> 10;
                    int cc = n0 & 1023;
                    int h = cc >> 6, d = cc & 63;
                    __nv_bfloat16* Hi = (which == 0) ? g_Qhi : (which == 1) ? g_Khi : g_Vhi;
                    __nv_bfloat16* Lo = (which == 0) ? g_Qlo : (which == 1) ? g_Klo : g_Vlo;
                    size_t idx = ((((size_t)bb * N_HEAD) + h) * SEQ + t) * HD + d;
                    __nv_bfloat16 h0 = __float2bfloat16(v0);
                    __nv_bfloat16 h1 = __float2bfloat16(v1);
                    *(__nv_bfloat162*)&Hi[idx] = __nv_bfloat162(h0, h1);
                    *(__nv_bfloat162*)&Lo[idx] = __nv_bfloat162(
                        __float2bfloat16(v0 - __bfloat162float(h0)),
                        __float2bfloat16(v1 - __bfloat162float(h1)));
                } else {
                    *(float2*)&Cout[(size_t)m * N + n0] = make_float2(v0, v1);
                }
            }
        }
    }
}

// ---------------------------------------------------------------------------
// HMMA flash attention: CTA = (b*h, 64-query block), 4 warps x 16 rows.
// S = Q K^T via bf16x3; softmax in C-fragment registers (quad shfl);
// P hi/lo repacked as A-frags; V via ldmatrix.trans; PV bf16x3.
// ---------------------------------------------------------------------------
#define FPITCH 144    // smem row pitch (bytes) for 64 bf16 rows (conflict-free)
#define FTILE  (64 * FPITCH)   // 9216 B

__global__ __launch_bounds__(128)
void flash_mma_kernel()
{
    extern __shared__ char fsm[];
    char* pQH = fsm;
    char* pKH = fsm + 2 * FTILE;
    char* pVH = fsm + 4 * FTILE;
    const uint32_t QH = smem_u32(pQH);
    const uint32_t KH = smem_u32(pKH);
    const uint32_t VH = smem_u32(pVH);

    int tid = threadIdx.x, lane = tid & 31, w = tid >> 5;
    int qb = (int)(gridDim.x - 1) - (int)blockIdx.x;    // heavy blocks first
    int bh = blockIdx.y;
    int q0 = qb * 64;
    size_t base = (size_t)bh * SEQ * HD;

    // load Q hi/lo tile
    {
        int r = tid >> 3, s = tid & 7;
#pragma unroll
        for (int it = 0; it < 4; it++) {
            int rr = r + it * 16;
            size_t off = base + (size_t)(q0 + rr) * HD + s * 8;
            *(uint4*)(pQH + rr * FPITCH + s * 16) = *(const uint4*)(g_Qhi + off);
            *(uint4*)(pQH + FTILE + rr * FPITCH + s * 16) = *(const uint4*)(g_Qlo + off);
        }
    }

    float m0 = -1e30f, m1 = -1e30f, l0 = 0.0f, l1 = 0.0f;
    float O[8][4];
#pragma unroll
    for (int i = 0; i < 8; i++)
#pragma unroll
        for (int j = 0; j < 4; j++) O[i][j] = 0.0f;

    for (int kb = 0; kb <= qb; kb++) {
        __syncthreads();   // prev tile compute done (and Q stores visible on kb=0)
        int k0 = kb * 64;
        {
            int r = tid >> 3, s = tid & 7;
#pragma unroll
            for (int it = 0; it < 4; it++) {
                int rr = r + it * 16;
                size_t off = base + (size_t)(k0 + rr) * HD + s * 8;
                *(uint4*)(pKH + rr * FPITCH + s * 16) = *(const uint4*)(g_Khi + off);
                *(uint4*)(pKH + FTILE + rr * FPITCH + s * 16) = *(const uint4*)(g_Klo + off);
                *(uint4*)(pVH + rr * FPITCH + s * 16) = *(const uint4*)(g_Vhi + off);
                *(uint4*)(pVH + FTILE + rr * FPITCH + s * 16) = *(const uint4*)(g_Vlo + off);
            }
        }
        __syncthreads();

        // ---- S = Q K^T (bf16x3) ----
        float S[8][4];
#pragma unroll
        for (int i = 0; i < 8; i++)
#pragma unroll
            for (int j = 0; j < 4; j++) S[i][j] = 0.0f;

        int bq = lane >> 3;
#pragma unroll
        for (int s = 0; s < 4; s++) {
            uint32_t ah[4], al[4];
            uint32_t ra = QH + (w * 16 + (lane & 15)) * FPITCH + (lane >> 4) * 16 + s * 32;
            ldsm_x4(ah[0], ah[1], ah[2], ah[3], ra);
            ldsm_x4(al[0], al[1], al[2], al[3], ra + FTILE);
#pragma unroll
            for (int nt = 0; nt < 4; nt++) {
                uint32_t bh_[4], bl_[4];
                uint32_t rb = KH + (nt * 16 + ((bq >> 1) << 3) + (lane & 7)) * FPITCH
                            + (bq & 1) * 16 + s * 32;
                ldsm_x4(bh_[0], bh_[1], bh_[2], bh_[3], rb);
                ldsm_x4(bl_[0], bl_[1], bl_[2], bl_[3], rb + FTILE);
                mma_bf16(S[2*nt],   ah, &bh_[0]);
                mma_bf16(S[2*nt],   ah, &bl_[0]);
                mma_bf16(S[2*nt],   al, &bh_[0]);
                mma_bf16(S[2*nt+1], ah, &bh_[2]);
                mma_bf16(S[2*nt+1], ah, &bl_[2]);
                mma_bf16(S[2*nt+1], al, &bh_[2]);
            }
        }

        // ---- scale + causal mask ----
#pragma unroll
        for (int nb = 0; nb < 8; nb++)
#pragma unroll
            for (int e = 0; e < 4; e++) S[nb][e] *= 0.125f;

        if (kb == qb) {
            int rl0 = w * 16 + (lane >> 2);
#pragma unroll
            for (int nb = 0; nb < 8; nb++) {
                int c = nb * 8 + 2 * (lane & 3);
                if (c     > rl0)     S[nb][0] = -1e30f;
                if (c + 1 > rl0)     S[nb][1] = -1e30f;
                if (c     > rl0 + 8) S[nb][2] = -1e30f;
                if (c + 1 > rl0 + 8) S[nb][3] = -1e30f;
            }
        }

        // ---- online softmax (rows r and r+8 per thread) ----
        float mx0 = -1e30f, mx1 = -1e30f;
#pragma unroll
        for (int nb = 0; nb < 8; nb++) {
            mx0 = fmaxf(mx0, fmaxf(S[nb][0], S[nb][1]));
            mx1 = fmaxf(mx1, fmaxf(S[nb][2], S[nb][3]));
        }
        mx0 = fmaxf(mx0, __shfl_xor_sync(0xffffffffu, mx0, 1));
        mx0 = fmaxf(mx0, __shfl_xor_sync(0xffffffffu, mx0, 2));
        mx1 = fmaxf(mx1, __shfl_xor_sync(0xffffffffu, mx1, 1));
        mx1 = fmaxf(mx1, __shfl_xor_sync(0xffffffffu, mx1, 2));
        float mn0 = fmaxf(m0, mx0), mn1 = fmaxf(m1, mx1);
        float corr0 = __expf(m0 - mn0), corr1 = __expf(m1 - mn1);
        float s0 = 0.0f, s1 = 0.0f;
#pragma unroll
        for (int nb = 0; nb < 8; nb++) {
            S[nb][0] = __expf(S[nb][0] - mn0); s0 += S[nb][0];
            S[nb][1] = __expf(S[nb][1] - mn0); s0 += S[nb][1];
            S[nb][2] = __expf(S[nb][2] - mn1); s1 += S[nb][2];
            S[nb][3] = __expf(S[nb][3] - mn1); s1 += S[nb][3];
        }
        s0 += __shfl_xor_sync(0xffffffffu, s0, 1);
        s0 += __shfl_xor_sync(0xffffffffu, s0, 2);
        s1 += __shfl_xor_sync(0xffffffffu, s1, 1);
        s1 += __shfl_xor_sync(0xffffffffu, s1, 2);
        l0 = l0 * corr0 + s0;
        l1 = l1 * corr1 + s1;
        m0 = mn0; m1 = mn1;
#pragma unroll
        for (int nb = 0; nb < 8; nb++) {
            O[nb][0] *= corr0; O[nb][1] *= corr0;
            O[nb][2] *= corr1; O[nb][3] *= corr1;
        }

        // ---- O += P V (bf16x3), P repacked from S frags ----
#pragma unroll
        for (int s = 0; s < 4; s++) {
            uint32_t pa_h[4], pa_l[4];
            split2(S[2*s][0],   S[2*s][1],   pa_h[0], pa_l[0]);
            split2(S[2*s][2],   S[2*s][3],   pa_h[1], pa_l[1]);
            split2(S[2*s+1][0], S[2*s+1][1], pa_h[2], pa_l[2]);
            split2(S[2*s+1][2], S[2*s+1][3], pa_h[3], pa_l[3]);
#pragma unroll
            for (int nt = 0; nt < 4; nt++) {
                uint32_t vh[4], vl[4];
                uint32_t rv = VH + (s * 16 + (lane & 7) + ((lane >> 3) & 1) * 8) * FPITCH
                            + nt * 32 + (lane >> 4) * 16;
                ldsm_x4_t(vh[0], vh[1], vh[2], vh[3], rv);
                ldsm_x4_t(vl[0], vl[1], vl[2], vl[3], rv + FTILE);
                mma_bf16(O[2*nt],   pa_h, &vh[0]);
                mma_bf16(O[2*nt],   pa_h, &vl[0]);
                mma_bf16(O[2*nt],   pa_l, &vh[0]);
                mma_bf16(O[2*nt+1], pa_h, &vh[2]);
                mma_bf16(O[2*nt+1], pa_h, &vl[2]);
                mma_bf16(O[2*nt+1], pa_l, &vh[2]);
            }
        }
    }

    // ---- normalize + write Y (bf16 hi/lo, [B,T,C]) ----
    int b = bh >> 4, h = bh & 15;
    int r0g = q0 + w * 16 + (lane >> 2);
    int dcol = 2 * (lane & 3);
    float inv0 = 1.0f / l0, inv1 = 1.0f / l1;
#pragma unroll
    for (int nb = 0; nb < 8; nb++) {
        int d = nb * 8 + dcol;
        {
            float f0 = O[nb][0] * inv0, f1 = O[nb][1] * inv0;
            size_t idx = ((size_t)(b * SEQ + r0g)) * C_EMBD + h * HD + d;
            __nv_bfloat16 h0 = __float2bfloat16(f0), h1 = __float2bfloat16(f1);
            *(__nv_bfloat162*)&g_Yhi[idx] = __nv_bfloat162(h0, h1);
            *(__nv_bfloat162*)&g_Ylo[idx] = __nv_bfloat162(
                __float2bfloat16(f0 - __bfloat162float(h0)),
                __float2bfloat16(f1 - __bfloat162float(h1)));
        }
        {
            float f2 = O[nb][2] * inv1, f3 = O[nb][3] * inv1;
            size_t idx = ((size_t)(b * SEQ + r0g + 8)) * C_EMBD + h * HD + d;
            __nv_bfloat16 h2 = __float2bfloat16(f2), h3 = __float2bfloat16(f3);
            *(__nv_bfloat162*)&g_Yhi[idx] = __nv_bfloat162(h2, h3);
            *(__nv_bfloat162*)&g_Ylo[idx] = __nv_bfloat162(
                __float2bfloat16(f2 - __bfloat162float(h2)),
                __float2bfloat16(f3 - __bfloat162float(h3)));
        }
    }
}

// ---------------------------------------------------------------------------
extern "C" void kernel_launch(void* const* d_in, const int* in_sizes, int n_in,
                              void* d_out, int out_size)
{
    const float* x      = (const float*)d_in[0];
    const float* W_attn = (const float*)d_in[1];
    const float* b_attn = (const float*)d_in[2];
    const float* W_proj = (const float*)d_in[3];
    const float* b_proj = (const float*)d_in[4];
    float* out = (float*)d_out;

    (void)in_sizes; (void)n_in; (void)out_size;

    static const int FLASH_SMEM = 6 * FTILE;                        // 55296 B
    static const int GEMM_SMEM  = 2 * STAGEB;                       // 81920 B
    cudaFuncSetAttribute(flash_mma_kernel,
                         cudaFuncAttributeMaxDynamicSharedMemorySize, FLASH_SMEM);
    cudaFuncSetAttribute(mma_gemm<0>,
                         cudaFuncAttributeMaxDynamicSharedMemorySize, GEMM_SMEM);
    cudaFuncSetAttribute(mma_gemm<1>,
                         cudaFuncAttributeMaxDynamicSharedMemorySize, GEMM_SMEM);

    // 0) prep: split x; transpose+split weights
    split_x_kernel<<<MTOT * C_EMBD / 4 / 256, 256>>>(x);
    wsplit_kernel<<<dim3(3 * C_EMBD / 32, C_EMBD / 32), dim3(32, 8)>>>(W_attn, 0, 3 * C_EMBD);
    wsplit_kernel<<<dim3(C_EMBD / 32, C_EMBD / 32), dim3(32, 8)>>>(W_proj, 1, C_EMBD);

    // 1) QKV GEMM (HMMA bf16x3) + bias -> Q/K/V bf16 hi/lo [B,H,T,hd]
    mma_gemm<0><<<dim3(3 * C_EMBD / 128, MTOT / 128), 256, GEMM_SMEM>>>(
        b_attn, nullptr, 3 * C_EMBD);

    // 2) causal flash attention (HMMA bf16x3) -> Yhi/Ylo
    flash_mma_kernel<<<dim3(SEQ / 64, BATCH * N_HEAD), 128, FLASH_SMEM>>>();

    // 3) output projection (HMMA bf16x3) + bias -> d_out
    mma_gemm<1><<<dim3(C_EMBD / 128, MTOT / 128), 256, GEMM_SMEM>>>(
        b_proj, out, C_EMBD);
}